// round 16
// baseline (speedup 1.0000x reference)
#include <cuda_runtime.h>
#include <cuda_fp16.h>
#include <cstdint>
#include <cstddef>

#define BATCH 4
#define SEQ   2048
#define EMB   1024
#define NH    16
#define HD    64
#define MTOT  (BATCH * SEQ)        /* 8192 */
#define KA    EMB                  /* 1024 */
#define KW    EMB                  /* 1024 */
#define BK    32
#define NSUP  16                   /* superiters per tile (2 k-iters each) */
#define LOG2E 1.44269504f
#define NEG_BIG (-1e30f)
#define BHS   ((size_t)BATCH * NH * SEQ)

#define GSK        288             /* stream-K grid; <= 2*148 guaranteed resident */
#define QKV_TILES  1536            /* 8 n x 64 m x 3 z */
#define OUT_TILES  512             /* 8 n x 64 m */

// ---------------- scratch (__device__ globals; no allocs) -------------------
__device__ __align__(1024) __half g_a2[3][(size_t)MTOT * KA];    // 3x16MB
__device__ __align__(1024) __half g_w1[4][(size_t)EMB * KW];     // 4x2MB
__device__ __align__(1024) __half g_q2[BHS * 64];
__device__ __align__(1024) __half g_k2[BHS * 64];
__device__ __align__(1024) __half g_vh[BHS * 64];
__device__ __align__(1024) float  g_part[GSK][256 * 64];         // 18.9MB partials
__device__ int g_flag[GSK];

// ---------------- PTX helpers ------------------------------------------------
__device__ __forceinline__ uint32_t smem_u32(const void* p) {
    uint32_t a;
    asm("{ .reg .u64 t; cvta.to.shared.u64 t, %1; cvt.u32.u64 %0, t; }" : "=r"(a) : "l"(p));
    return a;
}
#define CP_ASYNC16(dst, src) \
    asm volatile("cp.async.cg.shared.global [%0], [%1], 16;" :: "r"(dst), "l"(src) : "memory")
#define CP_COMMIT() asm volatile("cp.async.commit_group;" ::: "memory")
#define CP_WAIT1()  asm volatile("cp.async.wait_group 1;" ::: "memory")

__device__ __forceinline__ void ldsm4(uint32_t (&r)[4], uint32_t addr) {
    asm volatile("ldmatrix.sync.aligned.m8n8.x4.shared.b16 {%0,%1,%2,%3}, [%4];"
                 : "=r"(r[0]), "=r"(r[1]), "=r"(r[2]), "=r"(r[3]) : "r"(addr));
}
__device__ __forceinline__ void ldsm4t(uint32_t (&r)[4], uint32_t addr) {
    asm volatile("ldmatrix.sync.aligned.m8n8.x4.trans.shared.b16 {%0,%1,%2,%3}, [%4];"
                 : "=r"(r[0]), "=r"(r[1]), "=r"(r[2]), "=r"(r[3]) : "r"(addr));
}
__device__ __forceinline__ void mma16816h(float (&d)[4], const uint32_t (&a)[4],
                                          uint32_t b0, uint32_t b1) {
    asm volatile(
        "mma.sync.aligned.m16n8k16.row.col.f32.f16.f16.f32 "
        "{%0,%1,%2,%3}, {%4,%5,%6,%7}, {%8,%9}, {%0,%1,%2,%3};"
        : "+f"(d[0]), "+f"(d[1]), "+f"(d[2]), "+f"(d[3])
        : "r"(a[0]), "r"(a[1]), "r"(a[2]), "r"(a[3]), "r"(b0), "r"(b1));
}
__device__ __forceinline__ uint32_t pk2h(__half a, __half b) {
    __half2 t = __halves2half2(a, b);
    return *reinterpret_cast<uint32_t*>(&t);
}

// ---------------------------------------------------------------------------
// split_all: z<4 -> weights fp16; z>=4 -> activations fp16 (1024-wide rows)
// ---------------------------------------------------------------------------
__global__ __launch_bounds__(256)
void split_all(const float* __restrict__ q, const float* __restrict__ k,
               const float* __restrict__ v,
               const float* __restrict__ wq, const float* __restrict__ wk,
               const float* __restrict__ wv, const float* __restrict__ wo,
               __half* __restrict__ a2, __half* __restrict__ w1)
{
    const int z = blockIdx.y;
    if (z < 4) {
        const float* X = (z == 0) ? wq : (z == 1) ? wk : (z == 2) ? wv : wo;
        __half* Y = w1 + (size_t)z * EMB * KW;
        size_t idx = (size_t)blockIdx.x * 256 + threadIdx.x;
        float4 x = ((const float4*)X)[idx];
        *(uint2*)(Y + idx * 4) =
            make_uint2(pk2h(__float2half_rn(x.x), __float2half_rn(x.y)),
                       pk2h(__float2half_rn(x.z), __float2half_rn(x.w)));
    } else {
        const float* X = (z == 4) ? q : (z == 5) ? k : v;
        __half* Y = a2 + (size_t)(z - 4) * MTOT * KA;
        #pragma unroll
        for (int t = 0; t < 8; t++) {
            size_t idx = ((size_t)blockIdx.x * 8 + t) * 256 + threadIdx.x;
            float4 x = ((const float4*)X)[idx];
            *(uint2*)(Y + idx * 4) =
                make_uint2(pk2h(__float2half_rn(x.x), __float2half_rn(x.y)),
                           pk2h(__float2half_rn(x.z), __float2half_rn(x.w)));
        }
    }
}

// ---------------------------------------------------------------------------
// Segment compute: acc += A_tile @ W_tile^T over superiters [s0, s1).
// 6-stage cp.async pipeline in pairs, 1 barrier / superiter.
// ---------------------------------------------------------------------------
__device__ __forceinline__ void gemm_seg(
    const __half* __restrict__ Ap, const __half* __restrict__ Wp,
    int s0, int s1, float (&acc)[4][4][4], uint32_t sbase)
{
    const int tid  = threadIdx.x;
    const int lane = tid & 31;
    const int wid  = tid >> 5;
    const int wm   = wid >> 2;
    const int wn   = wid & 3;
    const int lrow = tid >> 2;
    const int lc   = tid & 3;

    const int arow = wm * 64 + (lane & 15);
    const int akh  = lane >> 4;
    const int aswz = (arow >> 1) & 3;
    const int brow = wn * 32 + (lane & 7) + ((lane & 16) ? 8 : 0);
    const int bkh  = (lane >> 3) & 1;
    const int bswz = (brow >> 1) & 3;

    // prologue: stages 0..3 = k-iters 2*s0 .. 2*s0+3 (guarded), 2 commit groups
    #pragma unroll
    for (int s = 0; s < 4; s++) {
        const int kit = 2 * s0 + s;
        if (kit < 2 * s1) {
            uint32_t sA = sbase + s * 16384;
            uint32_t sB = sA + 8192;
            const __half* ag = Ap + kit * BK + lc * 8;
            const __half* wg = Wp + kit * BK + lc * 8;
            #pragma unroll
            for (int h = 0; h < 2; h++) {
                int r  = lrow + h * 64;
                int cs = lc ^ ((r >> 1) & 3);
                CP_ASYNC16(sA + r * 64 + cs * 16, ag + (size_t)r * KA);
                CP_ASYNC16(sB + r * 64 + cs * 16, wg + (size_t)r * KW);
            }
        }
        if (s & 1) CP_COMMIT();
    }

    int st = 0;
    for (int j = s0; j < s1; j++) {
        CP_WAIT1();
        __syncthreads();

        #pragma unroll
        for (int half = 0; half < 2; half++) {
            const uint32_t sA = sbase + (st + half) * 16384;
            const uint32_t sB = sA + 8192;
            #pragma unroll
            for (int ks = 0; ks < 1; ks++) { }   // (kept minimal; ks loop below)
            #pragma unroll
            for (int ks = 0; ks < 2; ks++) {
                uint32_t a[4][4];
                uint32_t b[4][2];
                const int ac = ((ks * 2 + akh) ^ aswz) * 16;
                const int bc = ((ks * 2 + bkh) ^ bswz) * 16;
                #pragma unroll
                for (int mi = 0; mi < 4; mi++)
                    ldsm4(a[mi], sA + (arow + mi * 16) * 64 + ac);
                #pragma unroll
                for (int nj = 0; nj < 2; nj++) {
                    uint32_t t4[4];
                    ldsm4(t4, sB + (brow + nj * 16) * 64 + bc);
                    b[nj * 2][0]     = t4[0]; b[nj * 2][1]     = t4[1];
                    b[nj * 2 + 1][0] = t4[2]; b[nj * 2 + 1][1] = t4[3];
                }
                #pragma unroll
                for (int mi = 0; mi < 4; mi++)
                    #pragma unroll
                    for (int ni = 0; ni < 4; ni++)
                        mma16816h(acc[mi][ni], a[mi], b[ni][0], b[ni][1]);
            }
        }

        if (j + 2 < s1) {                    // prefetch superiter j+2
            int pf = st + 4; if (pf >= 6) pf -= 6;
            #pragma unroll
            for (int half = 0; half < 2; half++) {
                const int kit = 2 * (j + 2) + half;
                const uint32_t dA = sbase + (pf + half) * 16384;
                const uint32_t dB = dA + 8192;
                const __half* ag = Ap + kit * BK + lc * 8;
                const __half* wg = Wp + kit * BK + lc * 8;
                #pragma unroll
                for (int h = 0; h < 2; h++) {
                    int r  = lrow + h * 64;
                    int cs = lc ^ ((r >> 1) & 3);
                    CP_ASYNC16(dA + r * 64 + cs * 16, ag + (size_t)r * KA);
                    CP_ASYNC16(dB + r * 64 + cs * 16, wg + (size_t)r * KW);
                }
            }
        }
        CP_COMMIT();
        st += 2; if (st >= 6) st -= 6;
    }
}

// ---------------------------------------------------------------------------
// Epilogue: mode 0 fp32 out; mode 1 per-head fp16 64-wide out (with scale).
// ---------------------------------------------------------------------------
__device__ __forceinline__ void gemm_epi(
    float (&acc)[4][4][4], const float* __restrict__ bias,
    float* __restrict__ Cf, __half* __restrict__ OH,
    int mode, float scale, int m0, int n0)
{
    const int lane = threadIdx.x & 31;
    const int wid  = threadIdx.x >> 5;
    const int wm   = wid >> 2;
    const int wn   = wid & 3;
    const int trow = lane >> 2;
    const int tcol = (lane & 3) * 2;
    #pragma unroll
    for (int mi = 0; mi < 4; mi++) {
        const int row = m0 + wm * 64 + mi * 16 + trow;
        #pragma unroll
        for (int ni = 0; ni < 4; ni++) {
            const int col = n0 + wn * 32 + ni * 8 + tcol;
            const float b0 = __ldg(bias + col), b1 = __ldg(bias + col + 1);
            float v00 = acc[mi][ni][0] + b0, v01 = acc[mi][ni][1] + b1;
            float v10 = acc[mi][ni][2] + b0, v11 = acc[mi][ni][3] + b1;
            if (mode == 0) {
                *(float2*)(Cf + (size_t)row * EMB + col)       = make_float2(v00, v01);
                *(float2*)(Cf + (size_t)(row + 8) * EMB + col) = make_float2(v10, v11);
            } else {
                v00 *= scale; v01 *= scale; v10 *= scale; v11 *= scale;
                const int hh = col >> 6, d = col & 63;
                const size_t drow = ((size_t)((row >> 11) * NH + hh)) * SEQ + (row & 2047);
                *(uint32_t*)(OH + drow * 64 + d) =
                    pk2h(__float2half_rn(v00), __float2half_rn(v01));
                *(uint32_t*)(OH + (drow + 8) * 64 + d) =
                    pk2h(__float2half_rn(v10), __float2half_rn(v11));
            }
        }
    }
}

// ---------------------------------------------------------------------------
// Stream-K body shared by both GEMMs (tiles differ via mapping lambda-ish).
// qkv: tile -> (z, m0, n0); out: tile -> (m0, n0), mode 0.
// ---------------------------------------------------------------------------
__device__ __forceinline__ void streamk_run(
    int total_tiles, int is_qkv,
    const __half* __restrict__ Abase, const __half* __restrict__ Wbase,
    const float* __restrict__ bq, const float* __restrict__ bk,
    const float* __restrict__ bv,
    __half* __restrict__ q2, __half* __restrict__ k2, __half* __restrict__ vh,
    const float* __restrict__ bias_out, float* __restrict__ Cf,
    char* smem_raw)
{
    const uint32_t sbase = smem_u32(smem_raw);
    const int c = blockIdx.x;
    const long U = (long)total_tiles * NSUP;
    int u   = (int)((long)c * U / GSK);
    int end = (int)((long)(c + 1) * U / GSK);

    while (u < end) {
        const int tile = u >> 4;
        const int s0 = u & 15;
        int s1 = s0 + (end - u); if (s1 > NSUP) s1 = NSUP;

        int z, m0, n0;
        if (is_qkv) { z = tile >> 9; int r = tile & 511; m0 = (r >> 3) * 128; n0 = (r & 7) * 128; }
        else        { z = 0;         m0 = (tile >> 3) * 128; n0 = (tile & 7) * 128; }

        const __half* Ap = Abase + (size_t)z * MTOT * KA + (size_t)m0 * KA;
        const __half* Wp = Wbase + (size_t)z * EMB * KW + (size_t)n0 * KW;

        __syncthreads();   // smem reuse guard between segments

        float acc[4][4][4];
        #pragma unroll
        for (int i = 0; i < 4; i++)
            #pragma unroll
            for (int jj = 0; jj < 4; jj++)
                #pragma unroll
                for (int kk = 0; kk < 4; kk++) acc[i][jj][kk] = 0.f;

        gemm_seg(Ap, Wp, s0, s1, acc, sbase);

        const float* bias = is_qkv ? ((z == 0) ? bq : (z == 1) ? bk : bv) : bias_out;
        __half* OH = is_qkv ? ((z == 0) ? q2 : (z == 1) ? k2 : vh) : nullptr;
        const int mode = is_qkv ? 1 : 0;
        const float scale = (is_qkv && z == 0) ? 0.125f : 1.0f;

        if (s0 == 0 && s1 == NSUP) {
            gemm_epi(acc, bias, Cf, OH, mode, scale, m0, n0);
        } else if (s0 != 0) {
            // donor: first segment of this CTA; owner is CTA c-1
            float* dst = g_part[c] + threadIdx.x * 64;
            #pragma unroll
            for (int i = 0; i < 4; i++)
                #pragma unroll
                for (int jj = 0; jj < 4; jj++)
                    #pragma unroll
                    for (int kk = 0; kk < 4; kk++)
                        dst[i * 16 + jj * 4 + kk] = acc[i][jj][kk];
            __threadfence();
            __syncthreads();
            if (threadIdx.x == 0) atomicExch(&g_flag[c], 1);
        } else {
            // owner of split tile: donor is CTA c+1 (its FIRST segment)
            if (threadIdx.x == 0) {
                while (atomicAdd(&g_flag[c + 1], 0) == 0) { }
                __threadfence();
            }
            __syncthreads();
            const float* src = g_part[c + 1] + threadIdx.x * 64;
            #pragma unroll
            for (int i = 0; i < 4; i++)
                #pragma unroll
                for (int jj = 0; jj < 4; jj++)
                    #pragma unroll
                    for (int kk = 0; kk < 4; kk++)
                        acc[i][jj][kk] += src[i * 16 + jj * 4 + kk];
            gemm_epi(acc, bias, Cf, OH, mode, scale, m0, n0);
            __syncthreads();
            if (threadIdx.x == 0) atomicExch(&g_flag[c + 1], 0);
        }
        u += (s1 - s0);
    }
}

__global__ __launch_bounds__(256, 2)
void gemm_qkv_sk(const __half* __restrict__ Abase, const __half* __restrict__ Wbase,
                 const float* __restrict__ bq, const float* __restrict__ bk,
                 const float* __restrict__ bv,
                 __half* __restrict__ q2, __half* __restrict__ k2,
                 __half* __restrict__ vh)
{
    extern __shared__ __align__(1024) char smem_raw[];
    streamk_run(QKV_TILES, 1, Abase, Wbase, bq, bk, bv, q2, k2, vh,
                nullptr, nullptr, smem_raw);
}

__global__ __launch_bounds__(256, 2)
void gemm_out_sk(const __half* __restrict__ A, const __half* __restrict__ W,
                 const float* __restrict__ bias, float* __restrict__ Cf)
{
    extern __shared__ __align__(1024) char smem_raw[];
    streamk_run(OUT_TILES, 0, A, W, nullptr, nullptr, nullptr,
                nullptr, nullptr, nullptr, bias, Cf, smem_raw);
}

// ---------------------------------------------------------------------------
// HMMA flash attention (causal), single-fp16 operands (R15, unchanged).
// ---------------------------------------------------------------------------
__global__ __launch_bounds__(256, 2)
void attn_hmma(const __half* __restrict__ Q2, const __half* __restrict__ K2,
               const __half* __restrict__ VH, __half* __restrict__ A2)
{
    extern __shared__ __align__(1024) char smr[];
    const uint32_t sb = smem_u32(smr);
    const uint32_t QS = sb;                 // 2 slabs * 8192B
    const uint32_t KS = sb + 16384;         // 2 stages * 8192
    const uint32_t VS = sb + 32768;         // 2 stages * 8192

    const int tid  = threadIdx.x;
    const int lane = tid & 31;
    const int wid  = tid >> 5;
    const int bx   = gridDim.x - 1 - blockIdx.x;   // LPT: heavy first
    const int head = blockIdx.y;
    const int bz   = blockIdx.z;
    const int qb0  = bx * 128;
    const size_t bh = (size_t)(bz * NH + head);
    const int nkb  = 2 * bx + 2;

    const __half* Qp = Q2 + (bh * SEQ + qb0) * 64;
    const __half* Kp = K2 + bh * SEQ * 64;
    const __half* VHp = VH + bh * SEQ * 64;

    {
        const int r1 = tid >> 2, lc = tid & 3;
        #pragma unroll
        for (int kc = 0; kc < 2; kc++)
            #pragma unroll
            for (int h = 0; h < 2; h++) {
                int r = r1 + h * 64;
                int cs = lc ^ ((r >> 1) & 3);
                CP_ASYNC16(QS + kc * 8192 + r * 64 + cs * 16,
                           Qp + (size_t)r * 64 + kc * 32 + lc * 8);
            }
        int cs = lc ^ ((r1 >> 1) & 3);
        #pragma unroll
        for (int kc = 0; kc < 2; kc++)
            CP_ASYNC16(KS + kc * 4096 + r1 * 64 + cs * 16,
                       Kp + (size_t)r1 * 64 + kc * 32 + lc * 8);
        const int vr = tid >> 3, vc = tid & 7;
        #pragma unroll
        for (int h = 0; h < 2; h++) {
            int r = vr + h * 32;
            int pc = vc ^ (r & 7);
            CP_ASYNC16(VS + r * 128 + pc * 16, VHp + (size_t)r * 64 + vc * 8);
        }
        CP_COMMIT();
    }

    const int arow = wid * 16 + (lane & 15);
    const int akh  = lane >> 4;
    const int aswz = (arow >> 1) & 3;
    const int brow = (lane & 7) + ((lane & 16) ? 8 : 0);
    const int bkh  = (lane >> 3) & 1;
    const int bswz = (brow >> 1) & 3;
    const int vrow = (lane & 7) + 8 * ((lane >> 3) & 1);
    const int vchb = lane >> 4;
    const int vswz = lane & 7;

    float of[8][4];
    #pragma unroll
    for (int i = 0; i < 8; i++)
        #pragma unroll
        for (int j = 0; j < 4; j++) of[i][j] = 0.f;
    float mq[2] = { NEG_BIG, NEG_BIG };
    float lq[2] = { 0.f, 0.f };

    const int qrow0 = qb0 + wid * 16 + (lane >> 2);

    for (int kb = 0; kb < nkb; kb++) {
        const int st = kb & 1;
        const int kbase = kb * 64;

        if (kb + 1 < nkb) {
            const int nb = (kb + 1) * 64;
            const int s2 = st ^ 1;
            const int r1 = tid >> 2, lc = tid & 3;
            int cs = lc ^ ((r1 >> 1) & 3);
            #pragma unroll
            for (int kc = 0; kc < 2; kc++)
                CP_ASYNC16(KS + s2 * 8192 + kc * 4096 + r1 * 64 + cs * 16,
                           Kp + (size_t)(nb + r1) * 64 + kc * 32 + lc * 8);
            const int vr = tid >> 3, vc = tid & 7;
            #pragma unroll
            for (int h = 0; h < 2; h++) {
                int r = vr + h * 32;
                int pc = vc ^ (r & 7);
                CP_ASYNC16(VS + s2 * 8192 + r * 128 + pc * 16,
                           VHp + (size_t)(nb + r) * 64 + vc * 8);
            }
        }
        CP_COMMIT();
        CP_WAIT1();
        __syncthreads();

        float sf[8][4];
        #pragma unroll
        for (int i = 0; i < 8; i++)
            #pragma unroll
            for (int j = 0; j < 4; j++) sf[i][j] = 0.f;

        const uint32_t Kst = KS + st * 8192;
        #pragma unroll
        for (int g = 0; g < 2; g++) {
            #pragma unroll
            for (int ks = 0; ks < 2; ks++) {
                const int bc = ((ks * 2 + bkh) ^ bswz) * 16;
                uint32_t a[4];
                ldsm4(a, QS + g * 8192 + arow * 64 + (((ks * 2 + akh) ^ aswz) * 16));
                #pragma unroll
                for (int np = 0; np < 4; np++) {
                    uint32_t kf[4];
                    ldsm4(kf, Kst + g * 4096 + (np * 16 + brow) * 64 + bc);
                    mma16816h(sf[2 * np],     a, kf[0], kf[1]);
                    mma16816h(sf[2 * np + 1], a, kf[2], kf[3]);
                }
            }
        }

        if (kb >= nkb - 2) {
            #pragma unroll
            for (int nt = 0; nt < 8; nt++) {
                int col = kbase + nt * 8 + 2 * (lane & 3);
                if (col     > qrow0)     sf[nt][0] = NEG_BIG;
                if (col + 1 > qrow0)     sf[nt][1] = NEG_BIG;
                if (col     > qrow0 + 8) sf[nt][2] = NEG_BIG;
                if (col + 1 > qrow0 + 8) sf[nt][3] = NEG_BIG;
            }
        }

        #pragma unroll
        for (int h = 0; h < 2; h++) {
            float mloc = NEG_BIG;
            #pragma unroll
            for (int nt = 0; nt < 8; nt++)
                mloc = fmaxf(mloc, fmaxf(sf[nt][2 * h], sf[nt][2 * h + 1]));
            mloc = fmaxf(mloc, __shfl_xor_sync(0xffffffffu, mloc, 1));
            mloc = fmaxf(mloc, __shfl_xor_sync(0xffffffffu, mloc, 2));
            float mnew = fmaxf(mq[h], mloc);
            float corr = exp2f((mq[h] - mnew) * LOG2E);
            mq[h] = mnew;
            lq[h] *= corr;
            float ps = 0.f;
            #pragma unroll
            for (int nt = 0; nt < 8; nt++) {
                float p0 = exp2f((sf[nt][2 * h] - mnew) * LOG2E);
                float p1 = exp2f((sf[nt][2 * h + 1] - mnew) * LOG2E);
                sf[nt][2 * h] = p0; sf[nt][2 * h + 1] = p1;
                ps += p0 + p1;
                of[nt][2 * h] *= corr; of[nt][2 * h + 1] *= corr;
            }
            ps += __shfl_xor_sync(0xffffffffu, ps, 1);
            ps += __shfl_xor_sync(0xffffffffu, ps, 2);
            lq[h] += ps;
        }

        const uint32_t Vst = VS + st * 8192;
        #pragma unroll
        for (int kc2 = 0; kc2 < 4; kc2++) {
            const int j0 = 2 * kc2, j1 = j0 + 1;
            uint32_t ph[4];
            #pragma unroll
            for (int q = 0; q < 4; q++) {
                const float p0 = (q & 2) ? sf[j1][(q & 1) * 2]     : sf[j0][(q & 1) * 2];
                const float p1 = (q & 2) ? sf[j1][(q & 1) * 2 + 1] : sf[j0][(q & 1) * 2 + 1];
                ph[q] = pk2h(__float2half_rn(p0), __float2half_rn(p1));
            }
            const uint32_t rowoff = (kc2 * 16 + vrow) * 128;
            #pragma unroll
            for (int np = 0; np < 4; np++) {
                const int pc = (2 * np + vchb) ^ vswz;
                uint32_t bh4[4];
                ldsm4t(bh4, Vst + rowoff + pc * 16);
                mma16816h(of[2 * np],     ph, bh4[0], bh4[1]);
                mma16816h(of[2 * np + 1], ph, bh4[2], bh4[3]);
            }
        }
        __syncthreads();
    }

    const float inv0 = 1.f / lq[0];
    const float inv1 = 1.f / lq[1];
    const size_t ar0 = (size_t)bz * SEQ + qb0 + wid * 16 + (lane >> 2);
    const size_t ar1 = ar0 + 8;
    const int colb = head * 64 + 2 * (lane & 3);
    #pragma unroll
    for (int nt = 0; nt < 8; nt++) {
        int col = colb + nt * 8;
        float v0 = of[nt][0] * inv0, v1 = of[nt][1] * inv0;
        float v2 = of[nt][2] * inv1, v3 = of[nt][3] * inv1;
        *(uint32_t*)(A2 + ar0 * KA + col) =
            pk2h(__float2half_rn(v0), __float2half_rn(v1));
        *(uint32_t*)(A2 + ar1 * KA + col) =
            pk2h(__float2half_rn(v2), __float2half_rn(v3));
    }
}

// ---------------------------------------------------------------------------
extern "C" void kernel_launch(void* const* d_in, const int* in_sizes, int n_in,
                              void* d_out, int out_size)
{
    const float* query = (const float*)d_in[0];
    const float* key   = (const float*)d_in[1];
    const float* value = (const float*)d_in[2];
    const float* Wq = (const float*)d_in[4];  const float* bq = (const float*)d_in[5];
    const float* Wk = (const float*)d_in[6];  const float* bk = (const float*)d_in[7];
    const float* Wv = (const float*)d_in[8];  const float* bv = (const float*)d_in[9];
    const float* Wo = (const float*)d_in[10]; const float* bo = (const float*)d_in[11];
    float* out = (float*)d_out;

    __half *a2p, *w1p, *q2p, *k2p, *vhp;
    cudaGetSymbolAddress((void**)&a2p, g_a2);
    cudaGetSymbolAddress((void**)&w1p, g_w1);
    cudaGetSymbolAddress((void**)&q2p, g_q2);
    cudaGetSymbolAddress((void**)&k2p, g_k2);
    cudaGetSymbolAddress((void**)&vhp, g_vh);

    const int gsm = 6 * 16384;   // 96KB dynamic (keeps occ 2 with 128-reg cap)
    cudaFuncSetAttribute(gemm_qkv_sk, cudaFuncAttributeMaxDynamicSharedMemorySize, gsm);
    cudaFuncSetAttribute(gemm_out_sk, cudaFuncAttributeMaxDynamicSharedMemorySize, gsm);

    // all converts (4 weights + 3 activations) in one launch
    split_all<<<dim3(1024, 7), 256>>>(query, key, value, Wq, Wk, Wv, Wo, a2p, w1p);

    // QKV projections: stream-K persistent grid
    gemm_qkv_sk<<<GSK, 256, gsm>>>(a2p, w1p, bq, bk, bv, q2p, k2p, vhp);

    // attention -> a2 slot 0 directly
    const int asmem = 49152;
    cudaFuncSetAttribute(attn_hmma, cudaFuncAttributeMaxDynamicSharedMemorySize, asmem);
    attn_hmma<<<dim3(SEQ / 128, NH, BATCH), 256, asmem>>>(q2p, k2p, vhp, a2p);

    // out projection: stream-K persistent grid
    gemm_out_sk<<<GSK, 256, gsm>>>(a2p, w1p + 3 * (size_t)EMB * KW, bo, out);
}

// round 17
// speedup vs baseline: 1.0576x; 1.0576x over previous
#include <cuda_runtime.h>
#include <cuda_fp16.h>
#include <cstdint>
#include <cstddef>

#define BATCH 4
#define SEQ   2048
#define EMB   1024
#define NH    16
#define HD    64
#define MTOT  (BATCH * SEQ)        /* 8192 */
#define KA    EMB                  /* 1024: single fp16 A block */
#define KW    EMB                  /* 1024: single fp16 W block */
#define BK    32
#define NITER (KA / BK)            /* 32 */
#define LOG2E 1.44269504f
#define NEG_BIG (-1e30f)
#define BHS   ((size_t)BATCH * NH * SEQ)   /* 131072 per-head rows */

// ---------------- scratch (__device__ globals; no allocs) -------------------
__device__ __align__(1024) __half g_a2[3][(size_t)MTOT * KA];    // 3x16MB fp16
__device__ __align__(1024) __half g_w1[4][(size_t)EMB * KW];     // 4x2MB fp16
__device__ __align__(1024) __half g_q2[BHS * 64];   // [b,h,s][qh] 16MB
__device__ __align__(1024) __half g_k2[BHS * 64];   // [b,h,s][kh] 16MB
__device__ __align__(1024) __half g_vh[BHS * 64];   // [b,h,s][vh] 16MB

// ---------------- PTX helpers (baseline ISA: sm_80-era ops) -----------------
__device__ __forceinline__ uint32_t smem_u32(const void* p) {
    uint32_t a;
    asm("{ .reg .u64 t; cvta.to.shared.u64 t, %1; cvt.u32.u64 %0, t; }" : "=r"(a) : "l"(p));
    return a;
}
#define CP_ASYNC16(dst, src) \
    asm volatile("cp.async.cg.shared.global [%0], [%1], 16;" :: "r"(dst), "l"(src) : "memory")
#define CP_COMMIT() asm volatile("cp.async.commit_group;" ::: "memory")
#define CP_WAIT1()  asm volatile("cp.async.wait_group 1;" ::: "memory")

__device__ __forceinline__ void ldsm4(uint32_t (&r)[4], uint32_t addr) {
    asm volatile("ldmatrix.sync.aligned.m8n8.x4.shared.b16 {%0,%1,%2,%3}, [%4];"
                 : "=r"(r[0]), "=r"(r[1]), "=r"(r[2]), "=r"(r[3]) : "r"(addr));
}
__device__ __forceinline__ void ldsm4t(uint32_t (&r)[4], uint32_t addr) {
    asm volatile("ldmatrix.sync.aligned.m8n8.x4.trans.shared.b16 {%0,%1,%2,%3}, [%4];"
                 : "=r"(r[0]), "=r"(r[1]), "=r"(r[2]), "=r"(r[3]) : "r"(addr));
}
__device__ __forceinline__ void mma16816h(float (&d)[4], const uint32_t (&a)[4],
                                          uint32_t b0, uint32_t b1) {
    asm volatile(
        "mma.sync.aligned.m16n8k16.row.col.f32.f16.f16.f32 "
        "{%0,%1,%2,%3}, {%4,%5,%6,%7}, {%8,%9}, {%0,%1,%2,%3};"
        : "+f"(d[0]), "+f"(d[1]), "+f"(d[2]), "+f"(d[3])
        : "r"(a[0]), "r"(a[1]), "r"(a[2]), "r"(a[3]), "r"(b0), "r"(b1));
}
__device__ __forceinline__ uint32_t pk2h(__half a, __half b) {
    __half2 t = __halves2half2(a, b);
    return *reinterpret_cast<uint32_t*>(&t);
}

// ---------------------------------------------------------------------------
// split_all (one launch): z<4 -> weights fp16; z>=4 -> activations fp16
// ---------------------------------------------------------------------------
__global__ __launch_bounds__(256)
void split_all(const float* __restrict__ q, const float* __restrict__ k,
               const float* __restrict__ v,
               const float* __restrict__ wq, const float* __restrict__ wk,
               const float* __restrict__ wv, const float* __restrict__ wo,
               __half* __restrict__ a2, __half* __restrict__ w1)
{
    const int z = blockIdx.y;
    if (z < 4) {
        const float* X = (z == 0) ? wq : (z == 1) ? wk : (z == 2) ? wv : wo;
        __half* Y = w1 + (size_t)z * EMB * KW;
        size_t idx = (size_t)blockIdx.x * 256 + threadIdx.x;
        float4 x = ((const float4*)X)[idx];
        *(uint2*)(Y + idx * 4) =
            make_uint2(pk2h(__float2half_rn(x.x), __float2half_rn(x.y)),
                       pk2h(__float2half_rn(x.z), __float2half_rn(x.w)));
    } else {
        const float* X = (z == 4) ? q : (z == 5) ? k : v;
        __half* Y = a2 + (size_t)(z - 4) * MTOT * KA;
        #pragma unroll
        for (int t = 0; t < 8; t++) {
            size_t idx = ((size_t)blockIdx.x * 8 + t) * 256 + threadIdx.x;
            float4 x = ((const float4*)X)[idx];
            *(uint2*)(Y + idx * 4) =
                make_uint2(pk2h(__float2half_rn(x.x), __float2half_rn(x.y)),
                           pk2h(__float2half_rn(x.z), __float2half_rn(x.w)));
        }
    }
}

// ---------------------------------------------------------------------------
// GEMM core: C = A[*,1024] @ W[*,1024]^T + bias, fp16 MMA, K=1024.
// 256 threads / 8 warps, warp tile 64x32, 6-stage pipeline, 1 barrier / 2 iters.
// mode 0: fp32 out; mode 1: per-head fp16 64-wide out (with scale).
// ---------------------------------------------------------------------------
__device__ __forceinline__ void gemm_core(
    const __half* __restrict__ A, const __half* __restrict__ W,
    const float* __restrict__ bias, float* __restrict__ Cf,
    __half* __restrict__ OH,
    int mode, float scale, int m0, int n0, char* smem_raw)
{
    const uint32_t sbase = smem_u32(smem_raw);

    const int tid  = threadIdx.x;
    const int lane = tid & 31;
    const int wid  = tid >> 5;
    const int wm   = wid >> 2;
    const int wn   = wid & 3;

    const __half* Ap = A + (size_t)m0 * KA;
    const __half* Wp = W + (size_t)n0 * KW;

    const int lrow = tid >> 2;
    const int lc   = tid & 3;

    const int arow  = wm * 64 + (lane & 15);
    const int akh   = lane >> 4;
    const int aswz  = (arow >> 1) & 3;
    const int brow  = wn * 32 + (lane & 7) + ((lane & 16) ? 8 : 0);
    const int bkh   = (lane >> 3) & 1;
    const int bswz  = (brow >> 1) & 3;

    float acc[4][4][4];
    #pragma unroll
    for (int i = 0; i < 4; i++)
        #pragma unroll
        for (int j = 0; j < 4; j++)
            #pragma unroll
            for (int k = 0; k < 4; k++) acc[i][j][k] = 0.f;

    #pragma unroll
    for (int s = 0; s < 4; s++) {
        uint32_t sA = sbase + s * 16384;
        uint32_t sB = sA + 8192;
        const __half* ag = Ap + s * BK + lc * 8;
        const __half* wg = Wp + s * BK + lc * 8;
        #pragma unroll
        for (int h = 0; h < 2; h++) {
            int r  = lrow + h * 64;
            int cs = lc ^ ((r >> 1) & 3);
            CP_ASYNC16(sA + r * 64 + cs * 16, ag + (size_t)r * KA);
            CP_ASYNC16(sB + r * 64 + cs * 16, wg + (size_t)r * KW);
        }
        if (s & 1) CP_COMMIT();
    }

    int st = 0;
    for (int j = 0; j < NITER / 2; j++) {
        CP_WAIT1();
        __syncthreads();

        #pragma unroll
        for (int half = 0; half < 2; half++) {
            const uint32_t sA = sbase + (st + half) * 16384;
            const uint32_t sB = sA + 8192;
            #pragma unroll
            for (int ks = 0; ks < 2; ks++) {
                uint32_t a[4][4];
                uint32_t b[4][2];
                const int ac = ((ks * 2 + akh) ^ aswz) * 16;
                const int bc = ((ks * 2 + bkh) ^ bswz) * 16;
                #pragma unroll
                for (int mi = 0; mi < 4; mi++)
                    ldsm4(a[mi], sA + (arow + mi * 16) * 64 + ac);
                #pragma unroll
                for (int nj = 0; nj < 2; nj++) {
                    uint32_t t4[4];
                    ldsm4(t4, sB + (brow + nj * 16) * 64 + bc);
                    b[nj * 2][0]     = t4[0]; b[nj * 2][1]     = t4[1];
                    b[nj * 2 + 1][0] = t4[2]; b[nj * 2 + 1][1] = t4[3];
                }
                #pragma unroll
                for (int mi = 0; mi < 4; mi++)
                    #pragma unroll
                    for (int ni = 0; ni < 4; ni++)
                        mma16816h(acc[mi][ni], a[mi], b[ni][0], b[ni][1]);
            }
        }

        const int it0 = 2 * j + 4;
        if (it0 < NITER) {
            int pf = st + 4; if (pf >= 6) pf -= 6;
            #pragma unroll
            for (int half = 0; half < 2; half++) {
                const uint32_t dA = sbase + (pf + half) * 16384;
                const uint32_t dB = dA + 8192;
                const __half* ag = Ap + (it0 + half) * BK + lc * 8;
                const __half* wg = Wp + (it0 + half) * BK + lc * 8;
                #pragma unroll
                for (int h = 0; h < 2; h++) {
                    int r  = lrow + h * 64;
                    int cs = lc ^ ((r >> 1) & 3);
                    CP_ASYNC16(dA + r * 64 + cs * 16, ag + (size_t)r * KA);
                    CP_ASYNC16(dB + r * 64 + cs * 16, wg + (size_t)r * KW);
                }
            }
        }
        CP_COMMIT();
        st += 2; if (st >= 6) st -= 6;
    }

    // ---- epilogue ----
    const int trow = lane >> 2;
    const int tcol = (lane & 3) * 2;
    #pragma unroll
    for (int mi = 0; mi < 4; mi++) {
        const int row = m0 + wm * 64 + mi * 16 + trow;
        #pragma unroll
        for (int ni = 0; ni < 4; ni++) {
            const int col = n0 + wn * 32 + ni * 8 + tcol;
            const float b0 = __ldg(bias + col), b1 = __ldg(bias + col + 1);
            float v00 = acc[mi][ni][0] + b0, v01 = acc[mi][ni][1] + b1;
            float v10 = acc[mi][ni][2] + b0, v11 = acc[mi][ni][3] + b1;
            if (mode == 0) {
                *(float2*)(Cf + (size_t)row * EMB + col)       = make_float2(v00, v01);
                *(float2*)(Cf + (size_t)(row + 8) * EMB + col) = make_float2(v10, v11);
            } else {
                v00 *= scale; v01 *= scale; v10 *= scale; v11 *= scale;
                const int hh = col >> 6, d = col & 63;
                const size_t drow = ((size_t)((row >> 11) * NH + hh)) * SEQ + (row & 2047);
                *(uint32_t*)(OH + drow * 64 + d) =
                    pk2h(__float2half_rn(v00), __float2half_rn(v01));
                *(uint32_t*)(OH + (drow + 8) * 64 + d) =
                    pk2h(__float2half_rn(v10), __float2half_rn(v11));
            }
        }
    }
}

// z-batched QKV projections: z=0 -> q2 (scaled), z=1 -> k2, z=2 -> vh
__global__ __launch_bounds__(256, 2)
void gemm_qkv(const __half* __restrict__ Abase, const __half* __restrict__ Wbase,
              const float* __restrict__ bq, const float* __restrict__ bk,
              const float* __restrict__ bv,
              __half* __restrict__ q2, __half* __restrict__ k2,
              __half* __restrict__ vh)
{
    extern __shared__ __align__(1024) char smem_raw[];
    const int z = blockIdx.z;
    const __half* A = Abase + (size_t)z * MTOT * KA;
    const __half* W = Wbase + (size_t)z * EMB * KW;
    const float* bias = (z == 0) ? bq : (z == 1) ? bk : bv;
    __half* OH = (z == 0) ? q2 : (z == 1) ? k2 : vh;
    const float scale = (z == 0) ? 0.125f : 1.0f;
    gemm_core(A, W, bias, nullptr, OH, 1, scale,
              blockIdx.y * 128, blockIdx.x * 128, smem_raw);
}

// out projection -> fp32 d_out
__global__ __launch_bounds__(256, 2)
void gemm_out(const __half* __restrict__ A, const __half* __restrict__ W,
              const float* __restrict__ bias, float* __restrict__ Cf)
{
    extern __shared__ __align__(1024) char smem_raw[];
    gemm_core(A, W, bias, Cf, nullptr, 0, 1.0f,
              blockIdx.y * 128, blockIdx.x * 128, smem_raw);
}

// ---------------------------------------------------------------------------
// HMMA flash attention (causal), single-fp16 operands, paired key tiles:
// each pipeline stage holds 128 keys (2 x 64-tiles) -> half the barriers.
// smem: Q 16KB | K 2x16KB | V 2x16KB = 80KB, occ 2.
// ---------------------------------------------------------------------------
__global__ __launch_bounds__(256, 2)
void attn_hmma(const __half* __restrict__ Q2, const __half* __restrict__ K2,
               const __half* __restrict__ VH, __half* __restrict__ A2)
{
    extern __shared__ __align__(1024) char smr[];
    const uint32_t sb = smem_u32(smr);
    const uint32_t QS = sb;                 // 2 slabs * 8192B
    const uint32_t KS = sb + 16384;         // 2 stages * 16384 (2 sub-tiles ea.)
    const uint32_t VS = sb + 49152;         // 2 stages * 16384

    const int tid  = threadIdx.x;
    const int lane = tid & 31;
    const int wid  = tid >> 5;
    const int bx   = gridDim.x - 1 - blockIdx.x;   // LPT: heavy first
    const int head = blockIdx.y;
    const int bz   = blockIdx.z;
    const int qb0  = bx * 128;
    const size_t bh = (size_t)(bz * NH + head);
    const int npair = bx + 1;               // 128-key pairs (nkb = 2bx+2 even)

    const __half* Qp = Q2 + (bh * SEQ + qb0) * 64;
    const __half* Kp = K2 + bh * SEQ * 64;
    const __half* VHp = VH + bh * SEQ * 64;

    // ---- prologue: Q + pair 0 (128 keys of K and V) ----
    {
        const int r1 = tid >> 2, lc = tid & 3;
        #pragma unroll
        for (int kc = 0; kc < 2; kc++)
            #pragma unroll
            for (int h = 0; h < 2; h++) {
                int r = r1 + h * 64;
                int cs = lc ^ ((r >> 1) & 3);
                CP_ASYNC16(QS + kc * 8192 + r * 64 + cs * 16,
                           Qp + (size_t)r * 64 + kc * 32 + lc * 8);
            }
        int cs = lc ^ ((r1 >> 1) & 3);
        #pragma unroll
        for (int t2 = 0; t2 < 2; t2++)
            #pragma unroll
            for (int kc = 0; kc < 2; kc++)
                CP_ASYNC16(KS + t2 * 8192 + kc * 4096 + r1 * 64 + cs * 16,
                           Kp + (size_t)(t2 * 64 + r1) * 64 + kc * 32 + lc * 8);
        const int vr = tid >> 3, vc = tid & 7;
        #pragma unroll
        for (int t2 = 0; t2 < 2; t2++)
            #pragma unroll
            for (int h = 0; h < 2; h++) {
                int r = vr + h * 32;
                int pc = vc ^ (r & 7);
                CP_ASYNC16(VS + t2 * 8192 + r * 128 + pc * 16,
                           VHp + (size_t)(t2 * 64 + r) * 64 + vc * 8);
            }
        CP_COMMIT();
    }

    const int arow = wid * 16 + (lane & 15);
    const int akh  = lane >> 4;
    const int aswz = (arow >> 1) & 3;
    const int brow = (lane & 7) + ((lane & 16) ? 8 : 0);
    const int bkh  = (lane >> 3) & 1;
    const int bswz = (brow >> 1) & 3;
    const int vrow = (lane & 7) + 8 * ((lane >> 3) & 1);
    const int vchb = lane >> 4;
    const int vswz = lane & 7;

    float of[8][4];
    #pragma unroll
    for (int i = 0; i < 8; i++)
        #pragma unroll
        for (int j = 0; j < 4; j++) of[i][j] = 0.f;
    float mq[2] = { NEG_BIG, NEG_BIG };
    float lq[2] = { 0.f, 0.f };

    const int qrow0 = qb0 + wid * 16 + (lane >> 2);

    for (int p = 0; p < npair; p++) {
        const int st = p & 1;

        // prefetch pair p+1 into the other stage
        if (p + 1 < npair) {
            const int nb = (p + 1) * 128;
            const int s2 = st ^ 1;
            const int r1 = tid >> 2, lc = tid & 3;
            int cs = lc ^ ((r1 >> 1) & 3);
            #pragma unroll
            for (int t2 = 0; t2 < 2; t2++)
                #pragma unroll
                for (int kc = 0; kc < 2; kc++)
                    CP_ASYNC16(KS + s2 * 16384 + t2 * 8192 + kc * 4096 + r1 * 64 + cs * 16,
                               Kp + (size_t)(nb + t2 * 64 + r1) * 64 + kc * 32 + lc * 8);
            const int vr = tid >> 3, vc = tid & 7;
            #pragma unroll
            for (int t2 = 0; t2 < 2; t2++)
                #pragma unroll
                for (int h = 0; h < 2; h++) {
                    int r = vr + h * 32;
                    int pc = vc ^ (r & 7);
                    CP_ASYNC16(VS + s2 * 16384 + t2 * 8192 + r * 128 + pc * 16,
                               VHp + (size_t)(nb + t2 * 64 + r) * 64 + vc * 8);
                }
        }
        CP_COMMIT();
        CP_WAIT1();
        __syncthreads();

        // ---- two 64-key tiles from the resident pair ----
        #pragma unroll
        for (int t = 0; t < 2; t++) {
            const int kbase = p * 128 + t * 64;
            const uint32_t Kst = KS + st * 16384 + t * 8192;
            const uint32_t Vst = VS + st * 16384 + t * 8192;

            float sf[8][4];
            #pragma unroll
            for (int i = 0; i < 8; i++)
                #pragma unroll
                for (int j = 0; j < 4; j++) sf[i][j] = 0.f;

            #pragma unroll
            for (int g = 0; g < 2; g++) {
                #pragma unroll
                for (int ks = 0; ks < 2; ks++) {
                    const int bc = ((ks * 2 + bkh) ^ bswz) * 16;
                    uint32_t a[4];
                    ldsm4(a, QS + g * 8192 + arow * 64 + (((ks * 2 + akh) ^ aswz) * 16));
                    #pragma unroll
                    for (int np = 0; np < 4; np++) {
                        uint32_t kf[4];
                        ldsm4(kf, Kst + g * 4096 + (np * 16 + brow) * 64 + bc);
                        mma16816h(sf[2 * np],     a, kf[0], kf[1]);
                        mma16816h(sf[2 * np + 1], a, kf[2], kf[3]);
                    }
                }
            }

            if (p == npair - 1) {
                #pragma unroll
                for (int nt = 0; nt < 8; nt++) {
                    int col = kbase + nt * 8 + 2 * (lane & 3);
                    if (col     > qrow0)     sf[nt][0] = NEG_BIG;
                    if (col + 1 > qrow0)     sf[nt][1] = NEG_BIG;
                    if (col     > qrow0 + 8) sf[nt][2] = NEG_BIG;
                    if (col + 1 > qrow0 + 8) sf[nt][3] = NEG_BIG;
                }
            }

            #pragma unroll
            for (int h = 0; h < 2; h++) {
                float mloc = NEG_BIG;
                #pragma unroll
                for (int nt = 0; nt < 8; nt++)
                    mloc = fmaxf(mloc, fmaxf(sf[nt][2 * h], sf[nt][2 * h + 1]));
                mloc = fmaxf(mloc, __shfl_xor_sync(0xffffffffu, mloc, 1));
                mloc = fmaxf(mloc, __shfl_xor_sync(0xffffffffu, mloc, 2));
                float mnew = fmaxf(mq[h], mloc);
                float corr = exp2f((mq[h] - mnew) * LOG2E);
                mq[h] = mnew;
                lq[h] *= corr;
                float ps = 0.f;
                #pragma unroll
                for (int nt = 0; nt < 8; nt++) {
                    float p0 = exp2f((sf[nt][2 * h] - mnew) * LOG2E);
                    float p1 = exp2f((sf[nt][2 * h + 1] - mnew) * LOG2E);
                    sf[nt][2 * h] = p0; sf[nt][2 * h + 1] = p1;
                    ps += p0 + p1;
                    of[nt][2 * h] *= corr; of[nt][2 * h + 1] *= corr;
                }
                ps += __shfl_xor_sync(0xffffffffu, ps, 1);
                ps += __shfl_xor_sync(0xffffffffu, ps, 2);
                lq[h] += ps;
            }

            #pragma unroll
            for (int kc2 = 0; kc2 < 4; kc2++) {
                const int j0 = 2 * kc2, j1 = j0 + 1;
                uint32_t ph[4];
                #pragma unroll
                for (int q = 0; q < 4; q++) {
                    const float p0 = (q & 2) ? sf[j1][(q & 1) * 2]     : sf[j0][(q & 1) * 2];
                    const float p1 = (q & 2) ? sf[j1][(q & 1) * 2 + 1] : sf[j0][(q & 1) * 2 + 1];
                    ph[q] = pk2h(__float2half_rn(p0), __float2half_rn(p1));
                }
                const uint32_t rowoff = (kc2 * 16 + vrow) * 128;
                #pragma unroll
                for (int np = 0; np < 4; np++) {
                    const int pc = (2 * np + vchb) ^ vswz;
                    uint32_t bh4[4];
                    ldsm4t(bh4, Vst + rowoff + pc * 16);
                    mma16816h(of[2 * np],     ph, bh4[0], bh4[1]);
                    mma16816h(of[2 * np + 1], ph, bh4[2], bh4[3]);
                }
            }
        }
        __syncthreads();
    }

    const float inv0 = 1.f / lq[0];
    const float inv1 = 1.f / lq[1];
    const size_t ar0 = (size_t)bz * SEQ + qb0 + wid * 16 + (lane >> 2);
    const size_t ar1 = ar0 + 8;
    const int colb = head * 64 + 2 * (lane & 3);
    #pragma unroll
    for (int nt = 0; nt < 8; nt++) {
        int col = colb + nt * 8;
        float v0 = of[nt][0] * inv0, v1 = of[nt][1] * inv0;
        float v2 = of[nt][2] * inv1, v3 = of[nt][3] * inv1;
        *(uint32_t*)(A2 + ar0 * KA + col) =
            pk2h(__float2half_rn(v0), __float2half_rn(v1));
        *(uint32_t*)(A2 + ar1 * KA + col) =
            pk2h(__float2half_rn(v2), __float2half_rn(v3));
    }
}

// ---------------------------------------------------------------------------
extern "C" void kernel_launch(void* const* d_in, const int* in_sizes, int n_in,
                              void* d_out, int out_size)
{
    const float* query = (const float*)d_in[0];
    const float* key   = (const float*)d_in[1];
    const float* value = (const float*)d_in[2];
    const float* Wq = (const float*)d_in[4];  const float* bq = (const float*)d_in[5];
    const float* Wk = (const float*)d_in[6];  const float* bk = (const float*)d_in[7];
    const float* Wv = (const float*)d_in[8];  const float* bv = (const float*)d_in[9];
    const float* Wo = (const float*)d_in[10]; const float* bo = (const float*)d_in[11];
    float* out = (float*)d_out;

    __half *a2p, *w1p, *q2p, *k2p, *vhp;
    cudaGetSymbolAddress((void**)&a2p, g_a2);
    cudaGetSymbolAddress((void**)&w1p, g_w1);
    cudaGetSymbolAddress((void**)&q2p, g_q2);
    cudaGetSymbolAddress((void**)&k2p, g_k2);
    cudaGetSymbolAddress((void**)&vhp, g_vh);

    const int gsm = 6 * 16384;   // 96KB dynamic
    cudaFuncSetAttribute(gemm_qkv, cudaFuncAttributeMaxDynamicSharedMemorySize, gsm);
    cudaFuncSetAttribute(gemm_out, cudaFuncAttributeMaxDynamicSharedMemorySize, gsm);

    // all converts (4 weights + 3 activations) in one launch
    split_all<<<dim3(1024, 7), 256>>>(query, key, value, Wq, Wk, Wv, Wo, a2p, w1p);

    // QKV projections (z-batched) with fused fp16 per-head epilogues
    gemm_qkv<<<dim3(EMB / 128, MTOT / 128, 3), 256, gsm>>>(
        a2p, w1p, bq, bk, bv, q2p, k2p, vhp);

    // attention -> a2 slot 0 directly
    const int asmem = 81920;
    cudaFuncSetAttribute(attn_hmma, cudaFuncAttributeMaxDynamicSharedMemorySize, asmem);
    attn_hmma<<<dim3(SEQ / 128, NH, BATCH), 256, asmem>>>(q2p, k2p, vhp, a2p);

    // out projection -> d_out
    gemm_out<<<dim3(EMB / 128, MTOT / 128), 256, gsm>>>(
        a2p, w1p + 3 * (size_t)EMB * KW, bo, out);
}